// round 11
// baseline (speedup 1.0000x reference)
#include <cuda_runtime.h>
#include <cstdint>

// mysoftmax: per-pixel softmax over C=19 + variance propagation through the
// squared softmax Jacobian.
//   p = softmax(mu)
//   sigma_out_i = p_i^2 * ( S + (1 - 2 p_i) * sigma_i ),  S = sum_j p_j^2 sigma_j
//
// d_out layout: [p (B*N*C floats), sigma_out (B*N*C floats)]
//
// R11 (= R10 retry): R9 structure + L2 evict_last via the createpolicy /
// L2::cache_hint path (the bare .L2::evict_last qualifier is illegal on
// .v4.f32 for sm_100 ptxas). Theory: the 14.336us floor is the L2 dirty
// write-back drain (~40MB / 2.8TB/s); keeping output lines L2-resident
// across graph replays turns warm stores into dirty-hits with no DRAM drain.

static constexpr int C = 19;
static constexpr int WARPS = 4;
static constexpr int PIX_PER_WARP = 32;
static constexpr int PIX_PER_BLK = WARPS * PIX_PER_WARP;   // 128
static constexpr int WTILE  = PIX_PER_WARP * C;            // 608 floats
static constexpr int WTILE4 = WTILE / 4;                   // 152 float4
static constexpr int TILE   = PIX_PER_BLK * C;             // 2432 floats
static constexpr int NITER  = (WTILE4 + 31) / 32;          // 5 (last partial: 24 lanes)

__device__ __forceinline__ uint64_t make_evict_last_policy() {
    uint64_t policy;
    asm("createpolicy.fractional.L2::evict_last.b64 %0, 1.0;" : "=l"(policy));
    return policy;
}

__device__ __forceinline__ float4 ldg_hint(const float4* p, uint64_t policy) {
    float4 v;
    asm volatile("ld.global.L2::cache_hint.v4.f32 {%0,%1,%2,%3}, [%4], %5;"
                 : "=f"(v.x), "=f"(v.y), "=f"(v.z), "=f"(v.w)
                 : "l"(p), "l"(policy));
    return v;
}

__device__ __forceinline__ void stg_hint(float4* p, float4 v, uint64_t policy) {
    asm volatile("st.global.L2::cache_hint.v4.f32 [%0], {%1,%2,%3,%4}, %5;"
                 :: "l"(p), "f"(v.x), "f"(v.y), "f"(v.z), "f"(v.w), "l"(policy)
                 : "memory");
}

__global__ __launch_bounds__(PIX_PER_BLK)
void mysoftmax_kernel(const float* __restrict__ mu,
                      const float* __restrict__ sg,
                      float* __restrict__ out,
                      long long total_elems)   // B*N*C
{
    __shared__ __align__(16) float  se[TILE];    // exp(mu), warp-private slices
    __shared__ __align__(16) float  ssg[TILE];   // sigma,   warp-private slices
    __shared__ __align__(8)  float2 invS[PIX_PER_BLK];

    const int lane = threadIdx.x & 31;
    const int w    = threadIdx.x >> 5;
    const uint64_t pol = make_evict_last_policy();

    const long long gbase4 = (long long)blockIdx.x * (TILE / 4) + w * WTILE4;
    const int       sbase4 = w * WTILE4;          // float4 units
    const int       sbase  = w * WTILE;           // float units

    const float4* __restrict__ mu4 = reinterpret_cast<const float4*>(mu) + gbase4;
    const float4* __restrict__ sg4 = reinterpret_cast<const float4*>(sg) + gbase4;
    float4* se4  = reinterpret_cast<float4*>(se)  + sbase4;
    float4* ssg4 = reinterpret_cast<float4*>(ssg) + sbase4;

    // ---- phase 1: coalesced load (evict_last); exp in regs; stage smem ----
    float4 re[NITER];   // e = exp(mu), coalesced layout
    #pragma unroll
    for (int k = 0; k < NITER; k++) {
        int idx = lane + k * 32;
        if (idx < WTILE4) {
            const float4 m = ldg_hint(mu4 + idx, pol);
            float4 e;
            e.x = __expf(m.x); e.y = __expf(m.y);
            e.z = __expf(m.z); e.w = __expf(m.w);
            re[k] = e;
            se4[idx]  = e;
            ssg4[idx] = ldg_hint(sg4 + idx, pol);
        }
    }
    __syncwarp();

    // ---- phase 2: one pixel per lane; stride 19 -> conflict-free ----
    {
        const int row = sbase + lane * C;
        float s0 = 0.f, s1 = 0.f;       // sum e_j
        float q0 = 0.f, q1 = 0.f;       // sum e_j^2 * sigma_j
        #pragma unroll
        for (int j = 0; j < C; j++) {
            const float e = se[row + j];
            const float g = ssg[row + j];
            if (j & 1) { s1 += e; q1 = fmaf(e * e, g, q1); }
            else       { s0 += e; q0 = fmaf(e * e, g, q0); }
        }
        const float inv = __frcp_rn(s0 + s1);
        invS[w * PIX_PER_WARP + lane] = make_float2(inv, (q0 + q1) * inv * inv);
    }
    __syncwarp();

    // ---- phase 3: outputs from regs (+ smem sigma) -> gmem (evict_last) ----
    float4* __restrict__ outp = reinterpret_cast<float4*>(out) + gbase4;
    float4* __restrict__ outs = reinterpret_cast<float4*>(out + total_elems) + gbase4;

    #pragma unroll
    for (int k = 0; k < NITER; k++) {
        int idx = lane + k * 32;
        if (idx < WTILE4) {
            const float4 e4 = re[k];
            const float4 g4 = ssg4[idx];

            // float4 spans at most 2 pixels (warp-local pixel ids in [0,32))
            const unsigned e0 = (unsigned)idx * 4u;
            const unsigned pa = e0 / 19u;
            const unsigned pb = (e0 + 3u) / 19u;
            const float2 aa = invS[w * PIX_PER_WARP + pa];
            const float2 ab = invS[w * PIX_PER_WARP + pb];
            const unsigned lim = pb * 19u;

            float4 p4, s4;
            {
                const float2 a = (e0 + 0u < lim) ? aa : ab;
                const float p = e4.x * a.x;
                p4.x = p; s4.x = p * p * fmaf(1.0f - 2.0f * p, g4.x, a.y);
            }
            {
                const float2 a = (e0 + 1u < lim) ? aa : ab;
                const float p = e4.y * a.x;
                p4.y = p; s4.y = p * p * fmaf(1.0f - 2.0f * p, g4.y, a.y);
            }
            {
                const float2 a = (e0 + 2u < lim) ? aa : ab;
                const float p = e4.z * a.x;
                p4.z = p; s4.z = p * p * fmaf(1.0f - 2.0f * p, g4.z, a.y);
            }
            {
                const float p = e4.w * ab.x;
                p4.w = p; s4.w = p * p * fmaf(1.0f - 2.0f * p, g4.w, ab.y);
            }

            stg_hint(outp + idx, p4, pol);
            stg_hint(outs + idx, s4, pol);
        }
    }
}

extern "C" void kernel_launch(void* const* d_in, const int* in_sizes, int n_in,
                              void* d_out, int out_size)
{
    const float* mu = (const float*)d_in[0];
    const float* sg = (const float*)d_in[1];
    float* out = (float*)d_out;

    const long long total_elems = (long long)in_sizes[0];        // B*N*C = 4,980,736
    const int n_pix = (int)(total_elems / C);                    // 262,144
    const int n_blocks = n_pix / PIX_PER_BLK;                    // 2048

    mysoftmax_kernel<<<n_blocks, PIX_PER_BLK>>>(mu, sg, out, total_elems);
}

// round 13
// speedup vs baseline: 1.0323x; 1.0323x over previous
#include <cuda_runtime.h>

// mysoftmax: per-pixel softmax over C=19 + variance propagation through the
// squared softmax Jacobian.
//   p = softmax(mu)
//   sigma_out_i = p_i^2 * ( S + (1 - 2 p_i) * sigma_i ),  S = sum_j p_j^2 sigma_j
//
// d_out layout: [p (B*N*C floats), sigma_out (B*N*C floats)]
//
// R13 (= R12 resubmit; previous round died to a container-broker failure
// before running): R9 warp-autonomous structure (warp-private 32-pixel
// subtiles, exp computed once at load, barrier-free, conflict-free stride-19
// smem transpose), launched as 256-thread blocks / grid=1024. Kernel is at
// ~90% of the mixed-stream DRAM roofline (80MB in+out mandatory traffic);
// this is the last launch-shape knob.

static constexpr int C = 19;
static constexpr int WARPS = 8;
static constexpr int PIX_PER_WARP = 32;
static constexpr int PIX_PER_BLK = WARPS * PIX_PER_WARP;   // 256
static constexpr int WTILE  = PIX_PER_WARP * C;            // 608 floats
static constexpr int WTILE4 = WTILE / 4;                   // 152 float4
static constexpr int TILE   = PIX_PER_BLK * C;             // 4864 floats
static constexpr int NITER  = (WTILE4 + 31) / 32;          // 5 (last partial: 24 lanes)

__global__ __launch_bounds__(PIX_PER_BLK)
void mysoftmax_kernel(const float* __restrict__ mu,
                      const float* __restrict__ sg,
                      float* __restrict__ out,
                      long long total_elems)   // B*N*C
{
    __shared__ __align__(16) float  se[TILE];    // exp(mu), warp-private slices
    __shared__ __align__(16) float  ssg[TILE];   // sigma,   warp-private slices
    __shared__ __align__(8)  float2 invS[PIX_PER_BLK];

    const int lane = threadIdx.x & 31;
    const int w    = threadIdx.x >> 5;

    // this warp's float4 base into gmem and into its private smem slice
    const long long gbase4 = (long long)blockIdx.x * (TILE / 4) + w * WTILE4;
    const int       sbase4 = w * WTILE4;          // float4 units
    const int       sbase  = w * WTILE;           // float units

    const float4* __restrict__ mu4 = reinterpret_cast<const float4*>(mu) + gbase4;
    const float4* __restrict__ sg4 = reinterpret_cast<const float4*>(sg) + gbase4;
    float4* se4  = reinterpret_cast<float4*>(se)  + sbase4;
    float4* ssg4 = reinterpret_cast<float4*>(ssg) + sbase4;

    // ---- phase 1: coalesced load; exp in registers; stage to private smem ----
    float4 re[NITER];   // e = exp(mu), coalesced layout
    #pragma unroll
    for (int k = 0; k < NITER; k++) {
        int idx = lane + k * 32;
        if (idx < WTILE4) {
            const float4 m = mu4[idx];
            float4 e;
            e.x = __expf(m.x); e.y = __expf(m.y);
            e.z = __expf(m.z); e.w = __expf(m.w);
            re[k] = e;
            se4[idx]  = e;
            ssg4[idx] = sg4[idx];
        }
    }
    __syncwarp();

    // ---- phase 2: one pixel per lane; stride 19 -> conflict-free ----
    {
        const int row = sbase + lane * C;
        float s0 = 0.f, s1 = 0.f;       // sum e_j
        float q0 = 0.f, q1 = 0.f;       // sum e_j^2 * sigma_j
        #pragma unroll
        for (int j = 0; j < C; j++) {
            const float e = se[row + j];
            const float g = ssg[row + j];
            if (j & 1) { s1 += e; q1 = fmaf(e * e, g, q1); }
            else       { s0 += e; q0 = fmaf(e * e, g, q0); }
        }
        const float inv = __frcp_rn(s0 + s1);
        invS[w * PIX_PER_WARP + lane] = make_float2(inv, (q0 + q1) * inv * inv);
    }
    __syncwarp();

    // ---- phase 3: outputs from regs (+ smem sigma), straight to gmem ----
    float4* __restrict__ outp = reinterpret_cast<float4*>(out) + gbase4;
    float4* __restrict__ outs = reinterpret_cast<float4*>(out + total_elems) + gbase4;

    #pragma unroll
    for (int k = 0; k < NITER; k++) {
        int idx = lane + k * 32;
        if (idx < WTILE4) {
            const float4 e4 = re[k];
            const float4 g4 = ssg4[idx];

            // float4 spans at most 2 pixels (warp-local pixel ids in [0,32))
            const unsigned e0 = (unsigned)idx * 4u;
            const unsigned pa = e0 / 19u;
            const unsigned pb = (e0 + 3u) / 19u;
            const float2 aa = invS[w * PIX_PER_WARP + pa];
            const float2 ab = invS[w * PIX_PER_WARP + pb];
            const unsigned lim = pb * 19u;         // first element of pixel pb

            float4 p4, s4;
            {
                const float2 a = (e0 + 0u < lim) ? aa : ab;
                const float p = e4.x * a.x;
                p4.x = p; s4.x = p * p * fmaf(1.0f - 2.0f * p, g4.x, a.y);
            }
            {
                const float2 a = (e0 + 1u < lim) ? aa : ab;
                const float p = e4.y * a.x;
                p4.y = p; s4.y = p * p * fmaf(1.0f - 2.0f * p, g4.y, a.y);
            }
            {
                const float2 a = (e0 + 2u < lim) ? aa : ab;
                const float p = e4.z * a.x;
                p4.z = p; s4.z = p * p * fmaf(1.0f - 2.0f * p, g4.z, a.y);
            }
            {
                const float p = e4.w * ab.x;       // last element: pixel pb
                p4.w = p; s4.w = p * p * fmaf(1.0f - 2.0f * p, g4.w, ab.y);
            }

            outp[idx] = p4;
            outs[idx] = s4;
        }
    }
}

extern "C" void kernel_launch(void* const* d_in, const int* in_sizes, int n_in,
                              void* d_out, int out_size)
{
    const float* mu = (const float*)d_in[0];
    const float* sg = (const float*)d_in[1];
    float* out = (float*)d_out;

    const long long total_elems = (long long)in_sizes[0];        // B*N*C = 4,980,736
    const int n_pix = (int)(total_elems / C);                    // 262,144
    const int n_blocks = n_pix / PIX_PER_BLK;                    // 1024

    mysoftmax_kernel<<<n_blocks, PIX_PER_BLK>>>(mu, sg, out, total_elems);
}

// round 14
// speedup vs baseline: 1.1429x; 1.1071x over previous
#include <cuda_runtime.h>
#include <cstdint>

// mysoftmax: per-pixel softmax over C=19 + variance propagation through the
// squared softmax Jacobian.
//   p = softmax(mu)
//   sigma_out_i = p_i^2 * ( S + (1 - 2 p_i) * sigma_i ),  S = sum_j p_j^2 sigma_j
//
// d_out layout: [p (B*N*C floats), sigma_out (B*N*C floats)]
//
// R14: R13 winner (256-thread blocks, grid=1024, warp-private subtiles,
// exp-once, barrier-free) + sigma tile staged via cp.async.cg (LDGSTS):
// zero register transit, no STS issue slots, copy overlaps the mu-load/exp/
// e-staging work. Only the wait_group gates phase 2.

static constexpr int C = 19;
static constexpr int WARPS = 8;
static constexpr int PIX_PER_WARP = 32;
static constexpr int PIX_PER_BLK = WARPS * PIX_PER_WARP;   // 256
static constexpr int WTILE  = PIX_PER_WARP * C;            // 608 floats
static constexpr int WTILE4 = WTILE / 4;                   // 152 float4
static constexpr int TILE   = PIX_PER_BLK * C;             // 4864 floats
static constexpr int NITER  = (WTILE4 + 31) / 32;          // 5 (last partial: 24 lanes)

__device__ __forceinline__ void cp_async16(uint32_t dst, const void* src) {
    asm volatile("cp.async.cg.shared.global [%0], [%1], 16;\n"
                 :: "r"(dst), "l"(src));
}

__global__ __launch_bounds__(PIX_PER_BLK)
void mysoftmax_kernel(const float* __restrict__ mu,
                      const float* __restrict__ sg,
                      float* __restrict__ out,
                      long long total_elems)   // B*N*C
{
    __shared__ __align__(16) float  se[TILE];    // exp(mu), warp-private slices
    __shared__ __align__(16) float  ssg[TILE];   // sigma,   warp-private slices
    __shared__ __align__(8)  float2 invS[PIX_PER_BLK];

    const int lane = threadIdx.x & 31;
    const int w    = threadIdx.x >> 5;

    // this warp's float4 base into gmem and into its private smem slice
    const long long gbase4 = (long long)blockIdx.x * (TILE / 4) + w * WTILE4;
    const int       sbase4 = w * WTILE4;          // float4 units
    const int       sbase  = w * WTILE;           // float units

    const float4* __restrict__ mu4 = reinterpret_cast<const float4*>(mu) + gbase4;
    const float4* __restrict__ sg4 = reinterpret_cast<const float4*>(sg) + gbase4;
    float4* se4  = reinterpret_cast<float4*>(se)  + sbase4;
    float4* ssg4 = reinterpret_cast<float4*>(ssg) + sbase4;

    const uint32_t ssg_s = (uint32_t)__cvta_generic_to_shared(ssg4);

    // ---- phase 1 ----
    // sigma: gmem -> smem via cp.async (no registers, overlaps with mu work)
    #pragma unroll
    for (int k = 0; k < NITER; k++) {
        int idx = lane + k * 32;
        if (idx < WTILE4) cp_async16(ssg_s + (uint32_t)idx * 16u, sg4 + idx);
    }
    asm volatile("cp.async.commit_group;\n" ::: "memory");

    // mu: coalesced load, exp in registers, stage e to private smem
    float4 re[NITER];   // e = exp(mu), coalesced layout
    #pragma unroll
    for (int k = 0; k < NITER; k++) {
        int idx = lane + k * 32;
        if (idx < WTILE4) {
            const float4 m = mu4[idx];
            float4 e;
            e.x = __expf(m.x); e.y = __expf(m.y);
            e.z = __expf(m.z); e.w = __expf(m.w);
            re[k] = e;
            se4[idx] = e;
        }
    }
    asm volatile("cp.async.wait_group 0;\n" ::: "memory");
    __syncwarp();

    // ---- phase 2: one pixel per lane; stride 19 -> conflict-free ----
    {
        const int row = sbase + lane * C;
        float s0 = 0.f, s1 = 0.f;       // sum e_j
        float q0 = 0.f, q1 = 0.f;       // sum e_j^2 * sigma_j
        #pragma unroll
        for (int j = 0; j < C; j++) {
            const float e = se[row + j];
            const float g = ssg[row + j];
            if (j & 1) { s1 += e; q1 = fmaf(e * e, g, q1); }
            else       { s0 += e; q0 = fmaf(e * e, g, q0); }
        }
        const float inv = __frcp_rn(s0 + s1);
        invS[w * PIX_PER_WARP + lane] = make_float2(inv, (q0 + q1) * inv * inv);
    }
    __syncwarp();

    // ---- phase 3: outputs from regs (+ smem sigma), straight to gmem ----
    float4* __restrict__ outp = reinterpret_cast<float4*>(out) + gbase4;
    float4* __restrict__ outs = reinterpret_cast<float4*>(out + total_elems) + gbase4;

    #pragma unroll
    for (int k = 0; k < NITER; k++) {
        int idx = lane + k * 32;
        if (idx < WTILE4) {
            const float4 e4 = re[k];
            const float4 g4 = ssg4[idx];

            // float4 spans at most 2 pixels (warp-local pixel ids in [0,32))
            const unsigned e0 = (unsigned)idx * 4u;
            const unsigned pa = e0 / 19u;
            const unsigned pb = (e0 + 3u) / 19u;
            const float2 aa = invS[w * PIX_PER_WARP + pa];
            const float2 ab = invS[w * PIX_PER_WARP + pb];
            const unsigned lim = pb * 19u;         // first element of pixel pb

            float4 p4, s4;
            {
                const float2 a = (e0 + 0u < lim) ? aa : ab;
                const float p = e4.x * a.x;
                p4.x = p; s4.x = p * p * fmaf(1.0f - 2.0f * p, g4.x, a.y);
            }
            {
                const float2 a = (e0 + 1u < lim) ? aa : ab;
                const float p = e4.y * a.x;
                p4.y = p; s4.y = p * p * fmaf(1.0f - 2.0f * p, g4.y, a.y);
            }
            {
                const float2 a = (e0 + 2u < lim) ? aa : ab;
                const float p = e4.z * a.x;
                p4.z = p; s4.z = p * p * fmaf(1.0f - 2.0f * p, g4.z, a.y);
            }
            {
                const float p = e4.w * ab.x;       // last element: pixel pb
                p4.w = p; s4.w = p * p * fmaf(1.0f - 2.0f * p, g4.w, ab.y);
            }

            outp[idx] = p4;
            outs[idx] = s4;
        }
    }
}

extern "C" void kernel_launch(void* const* d_in, const int* in_sizes, int n_in,
                              void* d_out, int out_size)
{
    const float* mu = (const float*)d_in[0];
    const float* sg = (const float*)d_in[1];
    float* out = (float*)d_out;

    const long long total_elems = (long long)in_sizes[0];        // B*N*C = 4,980,736
    const int n_pix = (int)(total_elems / C);                    // 262,144
    const int n_blocks = n_pix / PIX_PER_BLK;                    // 1024

    mysoftmax_kernel<<<n_blocks, PIX_PER_BLK>>>(mu, sg, out, total_elems);
}